// round 8
// baseline (speedup 1.0000x reference)
#include <cuda_runtime.h>
#include <cstdint>

// Problem shape (fixed): input1/2 [4,3,720,1280] f32, flow3/4 [4,2,720,1280] f32
namespace {
constexpr int Wd  = 1280;
constexpr int Hd  = 720;
constexpr int Bd  = 4;
constexpr int HW  = Hd * Wd;
constexpr int BHW = Bd * HW;

constexpr float INV_LE  = 255.0f / 30.0f;              // 1 / LAMBDA_E
constexpr float INV2S2  = 1.0f / (2.0f * 1.5f * 1.5f); // 1/(2*sigma_d^2)
constexpr float THRESH_ = 1e-6f;
constexpr float EPS_    = 1e-6f;

constexpr int EX = 32, EY = 8;    // errfw tile (256 threads)
constexpr int PX = 16, PY = 8;    // splat threads; each thread = 2 px -> 32x8 px tile
constexpr int HLO = 8;            // splat smem halo (covers |flow| < 7)
constexpr int SWW = 32 + 2 * HLO; // 48
constexpr int SWH = PY + 2 * HLO; // 24
}

// Scratch: branch-indexed. acc4 = (p_r, p_g, p_b, pw), accR = rw.
__device__ float  g_fw   [2][BHW];
__device__ float4 g_acc4 [2][BHW];
__device__ float4 g_accR4[2][BHW / 4];

// ---------------------------------------------------------------------------
// Fused: photometric error (bilinear warp) + 3x3 box + fw = exp(-(e/le)^2),
// plus zeroing of this pixel's splat accumulators. grid.z = b + 4*br.
// ---------------------------------------------------------------------------
__device__ __forceinline__ float photo_err(
    const float* __restrict__ i1, const float* __restrict__ i2,
    const float* __restrict__ flow, int b, int x, int y)
{
    int r = y * Wd + x;
    float u = __ldg(flow + b * 2 * HW + r);
    float v = __ldg(flow + b * 2 * HW + HW + r);

    float gx = fminf(fmaxf((float)x + u, 0.f), (float)(Wd - 1));
    float gy = fminf(fmaxf((float)y + v, 0.f), (float)(Hd - 1));
    float x0f = floorf(gx), y0f = floorf(gy);
    int x0 = (int)x0f, y0 = (int)y0f;
    int x1 = min(x0 + 1, Wd - 1), y1 = min(y0 + 1, Hd - 1);
    float wx = gx - x0f, wy = gy - y0f;
    float w00 = (1.f - wx) * (1.f - wy);
    float w01 = wx * (1.f - wy);
    float w10 = (1.f - wx) * wy;
    float w11 = wx * wy;

    const float* i2b = i2 + b * 3 * HW;
    const float* i1b = i1 + b * 3 * HW;
    float e = 0.f;
#pragma unroll
    for (int c = 0; c < 3; c++) {
        const float* ip = i2b + c * HW;
        float wv = __ldg(ip + y0 * Wd + x0) * w00 + __ldg(ip + y0 * Wd + x1) * w01
                 + __ldg(ip + y1 * Wd + x0) * w10 + __ldg(ip + y1 * Wd + x1) * w11;
        e += fabsf(__ldg(i1b + c * HW + r) - wv);
    }
    return e * (1.f / 3.f);
}

__global__ void __launch_bounds__(EX * EY) k_errfw(
    const float* __restrict__ in1, const float* __restrict__ in2,
    const float* __restrict__ fl1, const float* __restrict__ fl2)
{
    __shared__ float serr[EY + 2][EX + 2];

    int br = blockIdx.z >> 2;
    int b  = blockIdx.z & 3;
    const float* i1   = br ? in2 : in1;
    const float* i2   = br ? in1 : in2;
    const float* flow = br ? fl2 : fl1;

    int bx = blockIdx.x * EX;
    int by = blockIdx.y * EY;
    int t  = threadIdx.y * EX + threadIdx.x;

    for (int idx = t; idx < (EY + 2) * (EX + 2); idx += EX * EY) {
        int j = idx / (EX + 2);
        int i = idx - j * (EX + 2);
        int ex = bx + i - 1;
        int ey = by + j - 1;
        float e = 0.f;
        if ((unsigned)ex < (unsigned)Wd && (unsigned)ey < (unsigned)Hd)
            e = photo_err(i1, i2, flow, b, ex, ey);
        serr[j][i] = e;
    }
    __syncthreads();

    int lx = threadIdx.x, ly = threadIdx.y;
    float s = 0.f;
#pragma unroll
    for (int j = 0; j < 3; j++)
#pragma unroll
        for (int i = 0; i < 3; i++)
            s += serr[ly + j][lx + i];

    float tt = s * (1.f / 9.f) * INV_LE;
    int x = bx + lx, y = by + ly;
    int pidx = b * HW + y * Wd + x;
    g_fw[br][pidx] = __expf(-tt * tt);

    g_acc4[br][pidx] = make_float4(0.f, 0.f, 0.f, 0.f);
    reinterpret_cast<float*>(g_accR4[br])[pidx] = 0.f;
}

// ---------------------------------------------------------------------------
// Forward gaussian splat, PAIRED: each thread handles 2 adjacent source px
// and merges taps both pixels share into a single red.v4 (linearity of add).
// Weights masked to each pixel's exact 4x4 window -> result identical to
// per-pixel scatter. Disjoint-window pairs (|dix0|>4 or |diy0|>4, ~0.5%)
// take a single-pixel fallback. rw accumulates in a smem tile (48x24,
// halo 8) flushed via cp.reduce.async.bulk; out-of-window rw taps fall back
// to global atomics. TAO_R truncation is dead (min w = exp(-8/4.5) > 0.05).
// grid.z = b + 4*br; both branches in one launch.
// ---------------------------------------------------------------------------
__device__ __forceinline__ void splat_one(
    float4* acc, float* accR, float* srw, int b,
    float tx, float ty, int ix0, int iy0,
    float s0, float s1, float s2, float f,
    int xw0, int yw0)
{
    float gxv[4], gyv[4];
#pragma unroll
    for (int k = 0; k < 4; k++) {
        float dx = tx - (float)(ix0 + k);
        float dy = ty - (float)(iy0 + k);
        gxv[k] = __expf(-dx * dx * INV2S2);
        gyv[k] = __expf(-dy * dy * INV2S2);
    }
#pragma unroll
    for (int j = 0; j < 4; j++) {
        int iy = iy0 + j;
        if ((unsigned)iy >= (unsigned)Hd) continue;
        int rowb = b * HW + iy * Wd;
        float gy = gyv[j];
        int sy = iy - yw0;
#pragma unroll
        for (int i = 0; i < 4; i++) {
            int ix = ix0 + i;
            if ((unsigned)ix >= (unsigned)Wd) continue;
            float w = gxv[i] * gy;
            asm volatile("red.global.add.v4.f32 [%0], {%1, %2, %3, %4};"
                         :: "l"(acc + rowb + ix), "f"(s0 * w), "f"(s1 * w),
                            "f"(s2 * w), "f"(f * w)
                         : "memory");
            int sx = ix - xw0;
            if ((unsigned)sx < (unsigned)SWW && (unsigned)sy < (unsigned)SWH)
                atomicAdd(srw + sy * SWW + sx, w);
            else
                atomicAdd(accR + rowb + ix, w);
        }
    }
}

__global__ void __launch_bounds__(PX * PY) k_splat(
    const float* __restrict__ in1, const float* __restrict__ in2,
    const float* __restrict__ fl1, const float* __restrict__ fl2)
{
    __shared__ __align__(16) float srw[SWH][SWW];

    int br = blockIdx.z >> 2;
    int b  = blockIdx.z & 3;
    const float* img  = br ? in2 : in1;
    const float* flow = br ? fl2 : fl1;

    int bx = blockIdx.x * 32;            // block covers 32 px in x
    int by = blockIdx.y * PY;
    int lx = threadIdx.x, ly = threadIdx.y;
    int t  = ly * PX + lx;
    int xa = bx + 2 * lx;                // pair: (xa, xa+1)
    int y  = by + ly;
    int r  = y * Wd + xa;
    int p  = b * HW + r;

    // zero smem tile
    {
        float4* sz = reinterpret_cast<float4*>(&srw[0][0]);
#pragma unroll
        for (int i = t; i < SWH * SWW / 4; i += PX * PY)
            sz[i] = make_float4(0.f, 0.f, 0.f, 0.f);
    }
    __syncthreads();

    {
        const float* fb = flow + b * 2 * HW;
        float2 u2  = *reinterpret_cast<const float2*>(fb + r);
        float2 v2  = *reinterpret_cast<const float2*>(fb + HW + r);
        float2 fw2 = *reinterpret_cast<const float2*>(&g_fw[br][p]);

        const float* imb = img + b * 3 * HW + r;
        float2 c0 = *reinterpret_cast<const float2*>(imb);
        float2 c1 = *reinterpret_cast<const float2*>(imb + HW);
        float2 c2 = *reinterpret_cast<const float2*>(imb + 2 * HW);

        float fa = fw2.x, fb_ = fw2.y;
        float sa0 = c0.x * fa, sa1 = c1.x * fa, sa2 = c2.x * fa;
        float sb0 = c0.y * fb_, sb1 = c1.y * fb_, sb2 = c2.y * fb_;

        float txa = (float)xa + u2.x,        tya = (float)y + v2.x;
        float txb = (float)(xa + 1) + u2.y,  tyb = (float)y + v2.y;
        int ix0a = (int)floorf(txa) - 1, iy0a = (int)floorf(tya) - 1;
        int ix0b = (int)floorf(txb) - 1, iy0b = (int)floorf(tyb) - 1;

        float4* acc  = g_acc4[br];
        float*  accR = reinterpret_cast<float*>(g_accR4[br]);
        int xw0 = bx - HLO, yw0 = by - HLO;

        if (abs(ix0a - ix0b) > 4 || abs(iy0a - iy0b) > 4) {
            // rare (~0.5%): disjoint windows, splat separately
            splat_one(acc, accR, &srw[0][0], b, txa, tya, ix0a, iy0a,
                      sa0, sa1, sa2, fa, xw0, yw0);
            splat_one(acc, accR, &srw[0][0], b, txb, tyb, ix0b, iy0b,
                      sb0, sb1, sb2, fb_, xw0, yw0);
        } else {
            int X0 = min(ix0a, ix0b);
            int Y0 = min(iy0a, iy0b);

            // per-column x-weights over the 8-wide bounding box, masked to
            // each pixel's 4-wide window
            float wxa[8], wxb[8];
#pragma unroll
            for (int i = 0; i < 8; i++) {
                int ix = X0 + i;
                float dxa = txa - (float)ix;
                float dxb = txb - (float)ix;
                float ea = __expf(-dxa * dxa * INV2S2);
                float eb = __expf(-dxb * dxb * INV2S2);
                wxa[i] = ((unsigned)(ix - ix0a) < 4u) ? ea : 0.f;
                wxb[i] = ((unsigned)(ix - ix0b) < 4u) ? eb : 0.f;
            }

#pragma unroll
            for (int j = 0; j < 8; j++) {
                int iy = Y0 + j;
                if ((unsigned)iy >= (unsigned)Hd) continue;
                float dya = tya - (float)iy;
                float dyb = tyb - (float)iy;
                float wya = ((unsigned)(iy - iy0a) < 4u)
                              ? __expf(-dya * dya * INV2S2) : 0.f;
                float wyb = ((unsigned)(iy - iy0b) < 4u)
                              ? __expf(-dyb * dyb * INV2S2) : 0.f;
                if (wya == 0.f && wyb == 0.f) continue;

                int rowb = b * HW + iy * Wd;
                int sy = iy - yw0;
#pragma unroll
                for (int i = 0; i < 8; i++) {
                    float wA = wxa[i] * wya;
                    float wB = wxb[i] * wyb;
                    float ws = wA + wB;
                    if (ws == 0.f) continue;
                    int ix = X0 + i;
                    if ((unsigned)ix >= (unsigned)Wd) continue;
                    asm volatile("red.global.add.v4.f32 [%0], {%1, %2, %3, %4};"
                                 :: "l"(acc + rowb + ix),
                                    "f"(sa0 * wA + sb0 * wB),
                                    "f"(sa1 * wA + sb1 * wB),
                                    "f"(sa2 * wA + sb2 * wB),
                                    "f"(fa * wA + fb_ * wB)
                                 : "memory");
                    int sx = ix - xw0;
                    if ((unsigned)sx < (unsigned)SWW && (unsigned)sy < (unsigned)SWH)
                        atomicAdd(&srw[sy][sx], ws);
                    else
                        atomicAdd(accR + rowb + ix, ws);
                }
            }
        }
    }
    __syncthreads();

    // flush rw tile: one bulk async reduce per valid row (threads 0..SWH-1)
    if (t < SWH) {
        int yy = by - HLO + t;
        if ((unsigned)yy < (unsigned)Hd) {
            int xs = max(bx - HLO, 0);
            int xe = min(bx + 32 + HLO, Wd);
            int nbytes = (xe - xs) * 4;                 // multiple of 16
            float* dst = reinterpret_cast<float*>(g_accR4[br]) + b * HW + yy * Wd + xs;
            uint32_t saddr = (uint32_t)__cvta_generic_to_shared(&srw[t][xs - (bx - HLO)]);
            asm volatile("fence.proxy.async.shared::cta;" ::: "memory");
            asm volatile("cp.reduce.async.bulk.global.shared::cta.bulk_group.add.f32 "
                         "[%0], [%1], %2;"
                         :: "l"(dst), "r"(saddr), "r"(nbytes) : "memory");
            asm volatile("cp.async.bulk.commit_group;" ::: "memory");
            asm volatile("cp.async.bulk.wait_group 0;" ::: "memory");
        }
    }
}

// ---------------------------------------------------------------------------
// Final adaptive blend — 4 px/thread, fully vectorized accesses.
// ---------------------------------------------------------------------------
__global__ void __launch_bounds__(256) k_blend(float* __restrict__ out) {
    int q = blockIdx.x * 256 + threadIdx.x;   // group of 4 pixels
    if (q >= BHW / 4) return;
    int p0 = q * 4;
    int b  = p0 / HW;
    int r  = p0 - b * HW;

    float4 R1v = g_accR4[0][q];
    float4 R2v = g_accR4[1][q];
    const float* R1p = &R1v.x;
    const float* R2p = &R2v.x;

    float4 o0, o1, o2;
    float* o0p = &o0.x; float* o1p = &o1.x; float* o2p = &o2.x;

#pragma unroll
    for (int k = 0; k < 4; k++) {
        float4 A = g_acc4[0][p0 + k];
        float4 C = g_acc4[1][p0 + k];
        float w1 = A.w / (R1p[k] + THRESH_);
        float w2 = C.w / (R2p[k] + THRESH_);
        float q1 = w1 / (A.w + THRESH_);
        float q2 = w2 / (C.w + THRESH_);
        float dn = 1.f / (w1 + w2 + EPS_);
        o0p[k] = (A.x * q1 + C.x * q2) * dn;
        o1p[k] = (A.y * q1 + C.y * q2) * dn;
        o2p[k] = (A.z * q1 + C.z * q2) * dn;
    }

    float* ob = out + b * 3 * HW + r;
    *reinterpret_cast<float4*>(ob)          = o0;
    *reinterpret_cast<float4*>(ob + HW)     = o1;
    *reinterpret_cast<float4*>(ob + 2 * HW) = o2;
}

// ---------------------------------------------------------------------------
extern "C" void kernel_launch(void* const* d_in, const int* in_sizes, int n_in,
                              void* d_out, int out_size)
{
    const float* i1 = (const float*)d_in[0];
    const float* i2 = (const float*)d_in[1];
    const float* f1 = (const float*)d_in[2];
    const float* f2 = (const float*)d_in[3];
    float* out = (float*)d_out;

    dim3 ge(Wd / EX, Hd / EY, Bd * 2);
    dim3 be(EX, EY, 1);
    dim3 gs(Wd / 32, Hd / PY, Bd * 2);
    dim3 bs(PX, PY, 1);
    int nb = (BHW / 4 + 255) / 256;

    k_errfw<<<ge, be>>>(i1, i2, f1, f2);   // launch 1 (both branches, zeros acc)
    k_splat<<<gs, bs>>>(i1, i2, f1, f2);   // launch 2 (both branches, paired)
    k_blend<<<nb, 256>>>(out);             // launch 3
}

// round 9
// speedup vs baseline: 1.0399x; 1.0399x over previous
#include <cuda_runtime.h>
#include <cstdint>

// Problem shape (fixed): input1/2 [4,3,720,1280] f32, flow3/4 [4,2,720,1280] f32
namespace {
constexpr int Wd  = 1280;
constexpr int Hd  = 720;
constexpr int Bd  = 4;
constexpr int HW  = Hd * Wd;
constexpr int BHW = Bd * HW;

constexpr float INV_LE  = 255.0f / 30.0f;              // 1 / LAMBDA_E
constexpr float INV2S2  = 1.0f / (2.0f * 1.5f * 1.5f); // 1/(2*sigma_d^2)
constexpr float THRESH_ = 1e-6f;
constexpr float EPS_    = 1e-6f;

constexpr int EX = 64, EY = 8;    // errfw pixel tile; 256 threads, 2 px/thread
constexpr int TX = 32, TY = 8;    // splat tile (256 threads) — round-4 config
constexpr int HLO = 8;            // splat smem halo (covers |flow| < 7)
constexpr int SWW = TX + 2 * HLO; // 48
constexpr int SWH = TY + 2 * HLO; // 24
}

// Scratch: branch-indexed. acc4 = (p_r, p_g, p_b, pw), accR = rw.
__device__ float  g_fw   [2][BHW];
__device__ float4 g_acc4 [2][BHW];
__device__ float4 g_accR4[2][BHW / 4];

// ---------------------------------------------------------------------------
// Fused: photometric error (bilinear warp) + 3x3 box + fw = exp(-(e/le)^2),
// plus zeroing of the splat accumulators. 2 px/thread, 64x8 tile.
// grid.z = b + 4*br.
// ---------------------------------------------------------------------------
__device__ __forceinline__ float photo_err(
    const float* __restrict__ i1, const float* __restrict__ i2,
    const float* __restrict__ flow, int b, int x, int y)
{
    int r = y * Wd + x;
    float u = __ldg(flow + b * 2 * HW + r);
    float v = __ldg(flow + b * 2 * HW + HW + r);

    float gx = fminf(fmaxf((float)x + u, 0.f), (float)(Wd - 1));
    float gy = fminf(fmaxf((float)y + v, 0.f), (float)(Hd - 1));
    float x0f = floorf(gx), y0f = floorf(gy);
    int x0 = (int)x0f, y0 = (int)y0f;
    int x1 = min(x0 + 1, Wd - 1), y1 = min(y0 + 1, Hd - 1);
    float wx = gx - x0f, wy = gy - y0f;
    float w00 = (1.f - wx) * (1.f - wy);
    float w01 = wx * (1.f - wy);
    float w10 = (1.f - wx) * wy;
    float w11 = wx * wy;

    const float* i2b = i2 + b * 3 * HW;
    const float* i1b = i1 + b * 3 * HW;
    float e = 0.f;
#pragma unroll
    for (int c = 0; c < 3; c++) {
        const float* ip = i2b + c * HW;
        float wv = __ldg(ip + y0 * Wd + x0) * w00 + __ldg(ip + y0 * Wd + x1) * w01
                 + __ldg(ip + y1 * Wd + x0) * w10 + __ldg(ip + y1 * Wd + x1) * w11;
        e += fabsf(__ldg(i1b + c * HW + r) - wv);
    }
    return e * (1.f / 3.f);
}

__global__ void __launch_bounds__(256) k_errfw(
    const float* __restrict__ in1, const float* __restrict__ in2,
    const float* __restrict__ fl1, const float* __restrict__ fl2)
{
    __shared__ float serr[EY + 2][EX + 2];

    int br = blockIdx.z >> 2;
    int b  = blockIdx.z & 3;
    const float* i1   = br ? in2 : in1;
    const float* i2   = br ? in1 : in2;
    const float* flow = br ? fl2 : fl1;

    int bx = blockIdx.x * EX;
    int by = blockIdx.y * EY;
    int t  = threadIdx.y * 32 + threadIdx.x;

    // fill (EY+2)x(EX+2) = 10x66 halo-err tile
    for (int idx = t; idx < (EY + 2) * (EX + 2); idx += 256) {
        int j = idx / (EX + 2);
        int i = idx - j * (EX + 2);
        int ex = bx + i - 1;
        int ey = by + j - 1;
        float e = 0.f;
        if ((unsigned)ex < (unsigned)Wd && (unsigned)ey < (unsigned)Hd)
            e = photo_err(i1, i2, flow, b, ex, ey);
        serr[j][i] = e;
    }
    __syncthreads();

    int lx = threadIdx.x, ly = threadIdx.y;
    int c0 = 2 * lx;                 // local column of first pixel

    // column sums over 3 rows for the 4 columns covering both pixels
    float cs0 = serr[ly][c0]     + serr[ly + 1][c0]     + serr[ly + 2][c0];
    float cs1 = serr[ly][c0 + 1] + serr[ly + 1][c0 + 1] + serr[ly + 2][c0 + 1];
    float cs2 = serr[ly][c0 + 2] + serr[ly + 1][c0 + 2] + serr[ly + 2][c0 + 2];
    float cs3 = serr[ly][c0 + 3] + serr[ly + 1][c0 + 3] + serr[ly + 2][c0 + 3];

    float sA = cs0 + cs1 + cs2;
    float sB = cs1 + cs2 + cs3;
    float tA = sA * (1.f / 9.f) * INV_LE;
    float tB = sB * (1.f / 9.f) * INV_LE;

    int x = bx + c0, y = by + ly;
    int pidx = b * HW + y * Wd + x;   // even -> 8B aligned

    float2 fw2 = make_float2(__expf(-tA * tA), __expf(-tB * tB));
    *reinterpret_cast<float2*>(&g_fw[br][pidx]) = fw2;

    float4 z4 = make_float4(0.f, 0.f, 0.f, 0.f);
    g_acc4[br][pidx]     = z4;
    g_acc4[br][pidx + 1] = z4;
    *reinterpret_cast<float2*>(reinterpret_cast<float*>(g_accR4[br]) + pidx) =
        make_float2(0.f, 0.f);
}

// ---------------------------------------------------------------------------
// Forward gaussian splat (round-4 structure, both branches in ONE launch):
//  - colors+pw: 16 red.v4 per pixel at L2 (irreducible 16B payloads)
//  - rw: shared-memory tile (48x24, halo 8) + cp.reduce.async.bulk row flush;
//    out-of-window taps (|flow| >= 7, ~never for N(0,1)) use global atomics.
//  - NEW: warp-internal x-permutation (lane l -> x offset ((l&7)<<2)|(l>>3))
//    spaces warp-mates 4 px apart so same-instruction reds hit distinct
//    addresses (removes intra-wavefront same-address serialization at LTS).
//    Same 128B lines touched per load -> coalescing unchanged.
// TAO_R truncation is dead (min tap weight exp(-8/4.5)=0.169 > 0.05).
// ---------------------------------------------------------------------------
__global__ void __launch_bounds__(TX * TY) k_splat(
    const float* __restrict__ in1, const float* __restrict__ in2,
    const float* __restrict__ fl1, const float* __restrict__ fl2)
{
    __shared__ __align__(16) float srw[SWH][SWW];

    int br = blockIdx.z >> 2;
    int b  = blockIdx.z & 3;
    const float* img  = br ? in2 : in1;
    const float* flow = br ? fl2 : fl1;

    int bx = blockIdx.x * TX;
    int by = blockIdx.y * TY;
    int lx = threadIdx.x, ly = threadIdx.y;
    int t  = ly * TX + lx;
    int px = ((lx & 7) << 2) | (lx >> 3);   // permuted x offset within warp
    int x  = bx + px, y = by + ly;
    int r  = y * Wd + x;
    int p  = b * HW + r;

    // zero smem tile
    {
        float4* sz = reinterpret_cast<float4*>(&srw[0][0]);
#pragma unroll
        for (int i = t; i < SWH * SWW / 4; i += TX * TY)
            sz[i] = make_float4(0.f, 0.f, 0.f, 0.f);
    }
    __syncthreads();

    {
        float u = __ldg(flow + b * 2 * HW + r);
        float v = __ldg(flow + b * 2 * HW + HW + r);
        float f = g_fw[br][p];

        const float* imb = img + b * 3 * HW + r;
        float s0 = __ldg(imb) * f;
        float s1 = __ldg(imb + HW) * f;
        float s2 = __ldg(imb + 2 * HW) * f;

        float tx = (float)x + u, ty = (float)y + v;
        float fx = floorf(tx), fy = floorf(ty);
        int ix0 = (int)fx - 1, iy0 = (int)fy - 1;

        float gxv[4], gyv[4];
#pragma unroll
        for (int k = 0; k < 4; k++) {
            float dx = tx - (fx + (float)(k - 1));
            float dy = ty - (fy + (float)(k - 1));
            gxv[k] = __expf(-dx * dx * INV2S2);
            gyv[k] = __expf(-dy * dy * INV2S2);
        }

        float4* acc  = g_acc4[br];
        float*  accR = reinterpret_cast<float*>(g_accR4[br]);
        int xw0 = bx - HLO, yw0 = by - HLO;

#pragma unroll
        for (int j = 0; j < 4; j++) {
            int iy = iy0 + j;
            if ((unsigned)iy >= (unsigned)Hd) continue;
            int rowb = b * HW + iy * Wd;
            float gy = gyv[j];
            int sy = iy - yw0;
#pragma unroll
            for (int i = 0; i < 4; i++) {
                int ix = ix0 + i;
                if ((unsigned)ix >= (unsigned)Wd) continue;
                float w = gxv[i] * gy;
                asm volatile("red.global.add.v4.f32 [%0], {%1, %2, %3, %4};"
                             :: "l"(acc + rowb + ix), "f"(s0 * w), "f"(s1 * w),
                                "f"(s2 * w), "f"(f * w)
                             : "memory");
                int sx = ix - xw0;
                if ((unsigned)sx < (unsigned)SWW && (unsigned)sy < (unsigned)SWH)
                    atomicAdd(&srw[sy][sx], w);
                else
                    atomicAdd(accR + rowb + ix, w);   // ~never taken for N(0,1) flow
            }
        }
    }
    __syncthreads();

    // flush rw tile: one bulk async reduce per valid row (threads 0..SWH-1)
    if (t < SWH) {
        int yy = by - HLO + t;
        if ((unsigned)yy < (unsigned)Hd) {
            int xs = max(bx - HLO, 0);
            int xe = min(bx + TX + HLO, Wd);
            int nbytes = (xe - xs) * 4;                 // multiple of 16
            float* dst = reinterpret_cast<float*>(g_accR4[br]) + b * HW + yy * Wd + xs;
            uint32_t saddr = (uint32_t)__cvta_generic_to_shared(&srw[t][xs - (bx - HLO)]);
            asm volatile("fence.proxy.async.shared::cta;" ::: "memory");
            asm volatile("cp.reduce.async.bulk.global.shared::cta.bulk_group.add.f32 "
                         "[%0], [%1], %2;"
                         :: "l"(dst), "r"(saddr), "r"(nbytes) : "memory");
            asm volatile("cp.async.bulk.commit_group;" ::: "memory");
            asm volatile("cp.async.bulk.wait_group 0;" ::: "memory");
        }
    }
}

// ---------------------------------------------------------------------------
// Final adaptive blend — 4 px/thread, fully vectorized accesses.
// ---------------------------------------------------------------------------
__global__ void __launch_bounds__(256) k_blend(float* __restrict__ out) {
    int q = blockIdx.x * 256 + threadIdx.x;   // group of 4 pixels
    if (q >= BHW / 4) return;
    int p0 = q * 4;
    int b  = p0 / HW;
    int r  = p0 - b * HW;

    float4 R1v = g_accR4[0][q];
    float4 R2v = g_accR4[1][q];
    const float* R1p = &R1v.x;
    const float* R2p = &R2v.x;

    float4 o0, o1, o2;
    float* o0p = &o0.x; float* o1p = &o1.x; float* o2p = &o2.x;

#pragma unroll
    for (int k = 0; k < 4; k++) {
        float4 A = g_acc4[0][p0 + k];
        float4 C = g_acc4[1][p0 + k];
        float w1 = A.w / (R1p[k] + THRESH_);
        float w2 = C.w / (R2p[k] + THRESH_);
        float q1 = w1 / (A.w + THRESH_);
        float q2 = w2 / (C.w + THRESH_);
        float dn = 1.f / (w1 + w2 + EPS_);
        o0p[k] = (A.x * q1 + C.x * q2) * dn;
        o1p[k] = (A.y * q1 + C.y * q2) * dn;
        o2p[k] = (A.z * q1 + C.z * q2) * dn;
    }

    float* ob = out + b * 3 * HW + r;
    *reinterpret_cast<float4*>(ob)          = o0;
    *reinterpret_cast<float4*>(ob + HW)     = o1;
    *reinterpret_cast<float4*>(ob + 2 * HW) = o2;
}

// ---------------------------------------------------------------------------
extern "C" void kernel_launch(void* const* d_in, const int* in_sizes, int n_in,
                              void* d_out, int out_size)
{
    const float* i1 = (const float*)d_in[0];
    const float* i2 = (const float*)d_in[1];
    const float* f1 = (const float*)d_in[2];
    const float* f2 = (const float*)d_in[3];
    float* out = (float*)d_out;

    dim3 ge(Wd / EX, Hd / EY, Bd * 2);
    dim3 be(32, EY, 1);
    dim3 gs(Wd / TX, Hd / TY, Bd * 2);
    dim3 bs(TX, TY, 1);
    int nb = (BHW / 4 + 255) / 256;

    k_errfw<<<ge, be>>>(i1, i2, f1, f2);   // launch 1 (both branches, zeros acc)
    k_splat<<<gs, bs>>>(i1, i2, f1, f2);   // launch 2 (both branches, merged)
    k_blend<<<nb, 256>>>(out);             // launch 3
}